// round 5
// baseline (speedup 1.0000x reference)
#include <cuda_runtime.h>
#include <cstdint>

// Problem constants
#define B        64
#define N_SV     63
#define HID      512
#define NEW_W    28
#define NEW_H    28
#define NCELL    (NEW_W * NEW_H)     // 784
#define HT       8                   // h-channels per block
#define NTHREADS 256
#define TILE_F   (HT * NCELL)        // 6272 floats per block tile
#define TILE_F4  (TILE_F / 4)        // 1568 float4
#define NPAIR    (N_SV * HT)         // 504 (agent, channel) pairs per block

// ---------------------------------------------------------------------------
// Single fused kernel. Each block exclusively owns output tile
// (b, h0..h0+8, all 784 cells).
//   Prologue: the <=504 enc values AND agent cells are loaded/computed FIRST,
//             so their global-load latency overlaps the fill phase.
//   Phase A : stream zeros for the tile straight to global with __stcs
//             (evict-first: write-once data, help L2 writeback).
//   barrier : orders zeros before patches within the block.
//   Phase B : <=2 no-return atomicMax (REDG.MAX) per thread patch the
//             occupied cells. Values <= 0 skipped (lose to the 0 init);
//             survivors >= 0 so int-compare on float bits is exact.
// ---------------------------------------------------------------------------
__global__ __launch_bounds__(NTHREADS)
void fused_raster_kernel(const float* __restrict__ pos,     // (B, N_SV, 3)
                         const float* __restrict__ enc,     // (B, N_SV, HID)
                         const int*   __restrict__ lengths, // (B,)
                         float* __restrict__ out)           // (B, HID, 28, 28)
{
    const int b   = blockIdx.x;
    const int h0  = blockIdx.y * HT;
    const int tid = threadIdx.x;

    __shared__ int sCell[N_SV];   // cell index per agent, -1 if invalid

    // --- Prologue 1: agent validity + cell index (first 63 threads) ---
    if (tid < N_SV) {
        int cell = -1;
        if (tid < lengths[b]) {
            const float x = pos[(b * N_SV + tid) * 3 + 0];
            const float y = pos[(b * N_SV + tid) * 3 + 1];
            // Match reference bit-exactly: (x * 28) / 224, trunc toward zero
            int xI = (int)((x * (float)NEW_W) / 224.0f);
            int yI = (int)((y * (float)NEW_H) / 224.0f);
            if (xI < NEW_W && yI < NEW_H) {
                if (xI < 0) xI = 0;
                if (yI < 0) yI = 0;
                cell = xI * NEW_H + yI;
            }
        }
        sCell[tid] = cell;
    }

    // --- Prologue 2: hoist this thread's enc loads (independent of zeros) ---
    // pairs i = tid and tid + NTHREADS  (504 total -> thread<248 has 2nd pair)
    const float* encB = enc + (size_t)b * N_SV * HID + h0;
    const int a0  = tid >> 3;             // first pair
    const int hh0 = tid & (HT - 1);
    float v0 = 0.f, v1 = 0.f;
    int a1 = 0, hh1 = 0;
    const bool p0 = (tid < NPAIR);
    const bool p1 = (tid + NTHREADS < NPAIR);
    if (p0) v0 = __ldg(encB + a0 * HID + hh0);
    if (p1) {
        a1  = (tid + NTHREADS) >> 3;
        hh1 = (tid + NTHREADS) & (HT - 1);
        v1  = __ldg(encB + a1 * HID + hh1);
    }

    // --- Phase A: stream zeros for the tile straight to global ---
    float* outB = out + ((size_t)b * HID + h0) * NCELL;
    float4* outB4 = (float4*)outB;
    const float4 z = make_float4(0.f, 0.f, 0.f, 0.f);
    // 1568 float4 / 256 threads = 6 full strides + 32-thread remainder
    #pragma unroll
    for (int k = 0; k < TILE_F4 / NTHREADS; k++)       // 6 iterations
        __stcs(outB4 + tid + k * NTHREADS, z);
    if (tid < TILE_F4 - (TILE_F4 / NTHREADS) * NTHREADS)   // last 32
        __stcs(outB4 + tid + (TILE_F4 / NTHREADS) * NTHREADS, z);

    // Order: sCell writes visible + zeros complete before patches.
    __syncthreads();

    // --- Phase B: patch occupied cells with no-return global atomicMax ---
    int* outBi = (int*)outB;
    if (p0 && v0 > 0.f) {
        const int c = sCell[a0];
        if (c >= 0) atomicMax(outBi + hh0 * NCELL + c, __float_as_int(v0));
    }
    if (p1 && v1 > 0.f) {
        const int c = sCell[a1];
        if (c >= 0) atomicMax(outBi + hh1 * NCELL + c, __float_as_int(v1));
    }
}

extern "C" void kernel_launch(void* const* d_in, const int* in_sizes, int n_in,
                              void* d_out, int out_size) {
    const float* pos     = (const float*)d_in[0];   // (B, N_SV, 3)
    const float* enc     = (const float*)d_in[1];   // (B, N_SV, HID)
    const int*   lengths = (const int*)d_in[2];     // (B,)

    dim3 grid(B, HID / HT);            // (64, 64) = 4096 blocks
    fused_raster_kernel<<<grid, NTHREADS>>>(pos, enc, lengths, (float*)d_out);
}

// round 7
// speedup vs baseline: 1.3881x; 1.3881x over previous
#include <cuda_runtime.h>
#include <cstdint>

// Problem constants
#define B        64
#define N_SV     63
#define HID      512
#define NEW_W    28
#define NEW_H    28
#define NCELL    (NEW_W * NEW_H)     // 784
#define HT       8                   // h-channels per block
#define NTHREADS 256
#define TILE_F   (HT * NCELL)        // 6272 floats per block tile
#define TILE_F8  (TILE_F / 8)        // 784 x 32B stores per tile

// 256-bit zero store with L2 evict_last priority. sm_103a requires .v8.b32
// for the evict_last modifier (Blackwell wide-store form). The output
// (102.8 MB) fits in the 126 MB L2; keeping its lines resident-dirty across
// graph replays lets each replay re-dirty them in place instead of paying
// DRAM writeback.
__device__ __forceinline__ void st_zero256_evict_last(void* p) {
    asm volatile(
        "st.global.L2::evict_last.v8.b32 [%0], {%1,%1,%1,%1,%1,%1,%1,%1};"
        :: "l"(p), "r"(0) : "memory");
}

// ---------------------------------------------------------------------------
// Single fused kernel. Each block exclusively owns output tile
// (b, h0..h0+8, all 784 cells).
//   Phase A : 256-bit zero stores straight to global (evict_last).
//   barrier : orders zeros before patches within the block.
//   Phase B : <=504 (agent,channel) pairs issue no-return atomicMax
//             (REDG.MAX). Values <= 0 skipped (lose to the 0 init);
//             survivors >= 0 so int-compare on float bits is exact.
//             enc read with __ldcs (streaming) to spare L2 ways.
// ---------------------------------------------------------------------------
__global__ __launch_bounds__(NTHREADS)
void fused_raster_kernel(const float* __restrict__ pos,     // (B, N_SV, 3)
                         const float* __restrict__ enc,     // (B, N_SV, HID)
                         const int*   __restrict__ lengths, // (B,)
                         float* __restrict__ out)           // (B, HID, 28, 28)
{
    const int b   = blockIdx.x;
    const int h0  = blockIdx.y * HT;
    const int tid = threadIdx.x;

    __shared__ int sCell[N_SV];   // cell index per agent, -1 if invalid

    // --- Stage 0: agent validity + cell index (first 63 threads) ---
    if (tid < N_SV) {
        int cell = -1;
        if (tid < lengths[b]) {
            const float x = pos[(b * N_SV + tid) * 3 + 0];
            const float y = pos[(b * N_SV + tid) * 3 + 1];
            // Reference math: int(x * 28 / 224), trunc toward zero
            int xI = (int)((x * (float)NEW_W) / 224.0f);
            int yI = (int)((y * (float)NEW_H) / 224.0f);
            if (xI < NEW_W && yI < NEW_H) {
                if (xI < 0) xI = 0;
                if (yI < 0) yI = 0;
                cell = xI * NEW_H + yI;
            }
        }
        sCell[tid] = cell;
    }

    // --- Phase A: zero the tile directly in global (256-bit, evict_last) ---
    // Tile base is 32B-aligned: (b*HID+h0)*NCELL*4 is a multiple of 3136.
    float* outB = out + ((size_t)b * HID + h0) * NCELL;
    char* outC = (char*)outB;
    // 784 x 32B stores / 256 threads = 3 full strides + 16-thread remainder
    #pragma unroll
    for (int k = 0; k < TILE_F8 / NTHREADS; k++)               // 3 iterations
        st_zero256_evict_last(outC + (size_t)(tid + k * NTHREADS) * 32);
    if (tid < TILE_F8 - (TILE_F8 / NTHREADS) * NTHREADS)       // last 16
        st_zero256_evict_last(outC + (size_t)(tid + (TILE_F8 / NTHREADS) * NTHREADS) * 32);

    // Order: sCell writes visible + zeros complete before patches.
    __syncthreads();

    // --- Phase B: patch occupied cells with no-return global atomicMax ---
    // 63 agents x 8 channels = 504 (a, hh) pairs; <=2 per thread.
    const float* encB = enc + (size_t)b * N_SV * HID + h0;
    int* outBi = (int*)outB;
    for (int i = tid; i < N_SV * HT; i += NTHREADS) {
        const int a    = i >> 3;          // i / HT
        const int hh   = i & (HT - 1);    // i % HT
        const int cell = sCell[a];
        if (cell >= 0) {
            const float v = __ldcs(encB + a * HID + hh);  // streaming read
            if (v > 0.f)
                atomicMax(outBi + hh * NCELL + cell, __float_as_int(v));
        }
    }
}

extern "C" void kernel_launch(void* const* d_in, const int* in_sizes, int n_in,
                              void* d_out, int out_size) {
    const float* pos     = (const float*)d_in[0];   // (B, N_SV, 3)
    const float* enc     = (const float*)d_in[1];   // (B, N_SV, HID)
    const int*   lengths = (const int*)d_in[2];     // (B,)

    dim3 grid(B, HID / HT);            // (64, 64) = 4096 blocks
    fused_raster_kernel<<<grid, NTHREADS>>>(pos, enc, lengths, (float*)d_out);
}